// round 4
// baseline (speedup 1.0000x reference)
#include <cuda_runtime.h>
#include <cstdint>
#include <cstddef>

// ---------------------------------------------------------------------------
// AttentionalPropagation, B=2, D=256, H=4, dim=64, N=M=4096.
// R4: tf32 mma.sync everywhere; 8-warp flash CTA; producer-side tf32 rounding.
// ---------------------------------------------------------------------------

#define BB 2
#define DD 256
#define HH 4

__device__ float g_q   [BB * HH * 4096 * 64];   // [b][h][n][di] (tf32, pre-scaled)
__device__ float g_k   [BB * HH * 4096 * 64];   // [b][h][m][di] (tf32)
__device__ float g_v   [BB * HH * 4096 * 64];   // [b][h][m][di] (tf32)
__device__ float g_attn[BB * DD * 4096];        // (B, D, N)
__device__ float g_msg [BB * DD * 4096];
__device__ float g_h   [BB * 2 * DD * 4096];    // (B, 2D, N)
__device__ float g_wts [655360];                // tf32-rounded weights

// weight offsets in g_wts
#define OFF_WQ 0
#define OFF_WK 65536
#define OFF_WV 131072
#define OFF_WM 196608
#define OFF_W1 262144
#define OFF_W2 524288

// ============================ PTX helpers ==================================
__device__ __forceinline__ uint32_t smem_u32(const void* p) {
    uint32_t a;
    asm("{ .reg .u64 t; cvta.to.shared.u64 t, %1; cvt.u32.u64 %0, t; }"
        : "=r"(a) : "l"(p));
    return a;
}
__device__ __forceinline__ uint32_t f2tf(float x) {
    uint32_t r; asm("cvt.rna.tf32.f32 %0, %1;" : "=r"(r) : "f"(x)); return r;
}
__device__ __forceinline__ float ex2(float x) {
    float r; asm("ex2.approx.f32 %0, %1;" : "=f"(r) : "f"(x)); return r;
}
__device__ __forceinline__ void mma8(float* d, const uint32_t* a,
                                     uint32_t b0, uint32_t b1) {
    asm volatile("mma.sync.aligned.m16n8k8.row.col.f32.tf32.tf32.f32 "
        "{%0,%1,%2,%3}, {%4,%5,%6,%7}, {%8,%9}, {%0,%1,%2,%3};"
        : "+f"(d[0]), "+f"(d[1]), "+f"(d[2]), "+f"(d[3])
        : "r"(a[0]), "r"(a[1]), "r"(a[2]), "r"(a[3]), "r"(b0), "r"(b1));
}
__device__ __forceinline__ void cp16(uint32_t s, const void* g) {
    asm volatile("cp.async.ca.shared.global [%0], [%1], 16;" :: "r"(s), "l"(g));
}
#define CP_COMMIT() asm volatile("cp.async.commit_group;" ::: "memory")
#define CP_WAIT(n)  asm volatile("cp.async.wait_group %0;" :: "n"(n) : "memory")

// ---------------------------------------------------------------------------
// round weights to tf32 once (deterministic, reruns every call)
// ---------------------------------------------------------------------------
__global__ void round_weights(const float* __restrict__ wq, const float* __restrict__ wk,
                              const float* __restrict__ wv, const float* __restrict__ wm,
                              const float* __restrict__ w1, const float* __restrict__ w2,
                              float* __restrict__ dst)
{
    int i = blockIdx.x * 256 + threadIdx.x;
    if (i >= 655360) return;
    float v;
    if      (i < OFF_WK) v = wq[i - OFF_WQ];
    else if (i < OFF_WV) v = wk[i - OFF_WK];
    else if (i < OFF_WM) v = wv[i - OFF_WV];
    else if (i < OFF_W1) v = wm[i - OFF_WM];
    else if (i < OFF_W2) v = w1[i - OFF_W1];
    else                 v = w2[i - OFF_W2];
    dst[i] = __uint_as_float(f2tf(v));
}

// ---------------------------------------------------------------------------
// tf32 mma flash attention. grid (N/128, H, B), 256 threads (8 warps),
// 16 q-rows per warp. Q/K/V arrive pre-rounded tf32; Q pre-scaled by
// 0.125*log2(e) so softmax is exp2 (ex2.approx). No-max softmax.
// ---------------------------------------------------------------------------
#define LDK 68
#define LDV 72
#define LDP 76
#define LDT 132

__global__ void __launch_bounds__(256)
flash_attn_tc(const float* __restrict__ q, const float* __restrict__ k,
              const float* __restrict__ v, float* __restrict__ attn,
              int N, int M)
{
    extern __shared__ float sm[];
    float* Ks = sm;                              // [2][64][LDK]
    float* Vs = sm + 2 * 64 * LDK;               // [2][64][LDV]
    float* Ps = sm + 2 * 64 * LDK + 2 * 64 * LDV;// [128][LDP] (Q stage / P / O^T)

    const int b  = blockIdx.z, h = blockIdx.y;
    const int n0 = blockIdx.x * 128;
    const int bh = b * HH + h;
    const int t  = threadIdx.x;
    const int wid = t >> 5, lane = t & 31;
    const int g = lane >> 2, tg = lane & 3;
    const int wr = wid * 16;

    const float* Kg = k + (size_t)bh * M * 64;
    const float* Vg = v + (size_t)bh * M * 64;

    // prefetch K/V tile 0  (64x64 each; 256 threads -> 4 float4 each)
    {
        uint32_t kd = smem_u32(Ks), vd = smem_u32(Vs);
        #pragma unroll
        for (int i = 0; i < 4; i++) {
            int idx = t + i * 256;
            int r = idx >> 4, c = (idx & 15) * 4;
            cp16(kd + (uint32_t)(r * LDK + c) * 4, Kg + r * 64 + c);
            cp16(vd + (uint32_t)(r * LDV + c) * 4, Vg + r * 64 + c);
        }
        CP_COMMIT();
    }

    // stage Q into Ps (raw: already scaled+rounded)
    {
        const float* Qg = q + ((size_t)bh * N + n0) * 64;
        #pragma unroll
        for (int i = 0; i < 8; i++) {
            int idx = t + i * 256;
            int r = idx >> 4, c = (idx & 15) * 4;
            *reinterpret_cast<float4*>(Ps + r * LDP + c) =
                *reinterpret_cast<const float4*>(Qg + r * 64 + c);
        }
    }
    __syncthreads();

    // persistent Q fragments (raw bits)
    uint32_t Qf[8][4];
    {
        int r0 = wr + g;
        #pragma unroll
        for (int kk = 0; kk < 8; kk++) {
            Qf[kk][0] = __float_as_uint(Ps[(r0    ) * LDP + kk * 8 + tg]);
            Qf[kk][1] = __float_as_uint(Ps[(r0 + 8) * LDP + kk * 8 + tg]);
            Qf[kk][2] = __float_as_uint(Ps[(r0    ) * LDP + kk * 8 + tg + 4]);
            Qf[kk][3] = __float_as_uint(Ps[(r0 + 8) * LDP + kk * 8 + tg + 4]);
        }
    }
    __syncthreads();

    float Of[8][4] = {};     // O accumulators per di-tile
    float lrow[2]  = {};     // row sums (rows r0, r0+8)

    const int nT = M / 64;
    for (int tt = 0; tt < nT; tt++) {
        const float* Kc = Ks + (tt & 1) * 64 * LDK;
        const float* Vc = Vs + (tt & 1) * 64 * LDV;

        if (tt + 1 < nT) {
            uint32_t kd = smem_u32(Ks + ((tt + 1) & 1) * 64 * LDK);
            uint32_t vd = smem_u32(Vs + ((tt + 1) & 1) * 64 * LDV);
            const float* Kn = Kg + (size_t)(tt + 1) * 64 * 64;
            const float* Vn = Vg + (size_t)(tt + 1) * 64 * 64;
            #pragma unroll
            for (int i = 0; i < 4; i++) {
                int idx = t + i * 256;
                int r = idx >> 4, c = (idx & 15) * 4;
                cp16(kd + (uint32_t)(r * LDK + c) * 4, Kn + r * 64 + c);
                cp16(vd + (uint32_t)(r * LDV + c) * 4, Vn + r * 64 + c);
            }
            CP_COMMIT();
            CP_WAIT(1);
        } else {
            CP_WAIT(0);
        }
        __syncthreads();

        // S = Q K^T   (raw-bit B fragments, pre-rounded)
        float Sc[8][4] = {};
        #pragma unroll
        for (int j = 0; j < 8; j++) {
            const float* Kr = Kc + (j * 8 + g) * LDK + tg;
            #pragma unroll
            for (int kk = 0; kk < 8; kk++) {
                uint32_t b0 = __float_as_uint(Kr[kk * 8]);
                uint32_t b1 = __float_as_uint(Kr[kk * 8 + 4]);
                mma8(Sc[j], Qf[kk], b0, b1);
            }
        }

        // exp2 + row-sum + store P (tf32-rounded); rows are warp-private
        {
            int r0 = wr + g;
            #pragma unroll
            for (int j = 0; j < 8; j++) {
                float e0 = ex2(Sc[j][0]);
                float e1 = ex2(Sc[j][1]);
                float e2 = ex2(Sc[j][2]);
                float e3 = ex2(Sc[j][3]);
                lrow[0] += e0 + e1;
                lrow[1] += e2 + e3;
                *reinterpret_cast<float2*>(Ps + (r0    ) * LDP + j * 8 + 2 * tg) =
                    make_float2(__uint_as_float(f2tf(e0)), __uint_as_float(f2tf(e1)));
                *reinterpret_cast<float2*>(Ps + (r0 + 8) * LDP + j * 8 + 2 * tg) =
                    make_float2(__uint_as_float(f2tf(e2)), __uint_as_float(f2tf(e3)));
            }
        }

        // O += P V
        {
            int r0 = wr + g;
            #pragma unroll
            for (int kk = 0; kk < 8; kk++) {
                uint32_t Pa[4];
                Pa[0] = __float_as_uint(Ps[(r0    ) * LDP + kk * 8 + tg]);
                Pa[1] = __float_as_uint(Ps[(r0 + 8) * LDP + kk * 8 + tg]);
                Pa[2] = __float_as_uint(Ps[(r0    ) * LDP + kk * 8 + tg + 4]);
                Pa[3] = __float_as_uint(Ps[(r0 + 8) * LDP + kk * 8 + tg + 4]);
                const float* Vr0 = Vc + (kk * 8 + tg    ) * LDV + g;
                const float* Vr1 = Vc + (kk * 8 + tg + 4) * LDV + g;
                #pragma unroll
                for (int j = 0; j < 8; j++) {
                    uint32_t b0 = __float_as_uint(Vr0[j * 8]);
                    uint32_t b1 = __float_as_uint(Vr1[j * 8]);
                    mma8(Of[j], Pa, b0, b1);
                }
            }
        }
        __syncthreads();
    }

    // finalize l across the 4-lane column group
    {
        #pragma unroll
        for (int r = 0; r < 2; r++) {
            float s = lrow[r];
            s += __shfl_xor_sync(0xffffffffu, s, 1);
            s += __shfl_xor_sync(0xffffffffu, s, 2);
            lrow[r] = 1.0f / s;
        }
    }

    __syncthreads();
    // stage O transposed: Pt[di][n_local]
    float* Pt = Ps;
    {
        int r0 = wr + g;
        #pragma unroll
        for (int j = 0; j < 8; j++) {
            Pt[(j * 8 + 2 * tg    ) * LDT + r0    ] = Of[j][0] * lrow[0];
            Pt[(j * 8 + 2 * tg + 1) * LDT + r0    ] = Of[j][1] * lrow[0];
            Pt[(j * 8 + 2 * tg    ) * LDT + r0 + 8] = Of[j][2] * lrow[1];
            Pt[(j * 8 + 2 * tg + 1) * LDT + r0 + 8] = Of[j][3] * lrow[1];
        }
    }
    __syncthreads();

    // coalesced store into (B, D, N), channel = di*H + h
    #pragma unroll
    for (int cc = 0; cc < 8; cc++) {
        int di = wid * 8 + cc;
        float4 val = *reinterpret_cast<const float4*>(Pt + di * LDT + lane * 4);
        *reinterpret_cast<float4*>(
            attn + ((size_t)(b * DD + di * HH + h)) * N + n0 + lane * 4) = val;
    }
}

// ---------------------------------------------------------------------------
// tf32 mma projection GEMM: out[b,o,n] = sum_i W[o,i] X[b,i,n] + bias[o]
// W is pre-rounded tf32 (raw-bit fragments). X fragments cvt at load.
// CTA 256 thr, tile 128x128, BK=32, double-buffered cp.async.
// mode 0: (B,OC,N). mode 1: [b][h][n][di] head-permute, *oscale, tf32-round.
// ---------------------------------------------------------------------------
#define LDWM 36
#define LDXM 136

__global__ void __launch_bounds__(256)
gemm_tc(const float* __restrict__ W, const float* __restrict__ bias,
        const float* __restrict__ X0, int C0, const float* __restrict__ X1,
        float* __restrict__ out, int OC, int IC, int N, int mode, float oscale)
{
    extern __shared__ float sm[];
    float* Ws = sm;                       // [2][128][LDWM]
    float* Xs = sm + 2 * 128 * LDWM;      // [2][32][LDXM]

    const int b  = blockIdx.z;
    const int o0 = blockIdx.y * 128;
    const int n0 = blockIdx.x * 128;
    const int t  = threadIdx.x;
    const int wid = t >> 5, lane = t & 31;
    const int g = lane >> 2, tg = lane & 3;
    const int wo = (wid & 1) * 64;
    const int wn = (wid >> 1) * 32;

    auto stage = [&](int buf, int k0) {
        uint32_t wd = smem_u32(Ws + buf * 128 * LDWM);
        uint32_t xd = smem_u32(Xs + buf * 32 * LDXM);
        #pragma unroll
        for (int i = 0; i < 4; i++) {
            int idx = t + i * 256;
            int r = idx >> 3, c = (idx & 7) * 4;
            cp16(wd + (uint32_t)(r * LDWM + c) * 4,
                 W + (size_t)(o0 + r) * IC + k0 + c);
        }
        #pragma unroll
        for (int i = 0; i < 4; i++) {
            int idx = t + i * 256;
            int r = idx >> 5, c = (idx & 31) * 4;
            int ch = k0 + r;
            const float* src = (ch < C0)
                ? (X0 + ((size_t)b * C0 + ch) * N)
                : (X1 + ((size_t)b * (IC - C0) + (ch - C0)) * N);
            cp16(xd + (uint32_t)(r * LDXM + c) * 4, src + n0 + c);
        }
        CP_COMMIT();
    };

    stage(0, 0);
    float acc[4][4][4] = {};

    const int nK = IC / 32;
    for (int kt = 0; kt < nK; kt++) {
        if (kt + 1 < nK) { stage((kt + 1) & 1, (kt + 1) * 32); CP_WAIT(1); }
        else             { CP_WAIT(0); }
        __syncthreads();
        const float* Wc = Ws + (kt & 1) * 128 * LDWM;
        const float* Xc = Xs + (kt & 1) * 32 * LDXM;

        #pragma unroll
        for (int ks = 0; ks < 4; ks++) {
            uint32_t Af[4][4];
            #pragma unroll
            for (int mt = 0; mt < 4; mt++) {
                int r0 = wo + mt * 16 + g;
                Af[mt][0] = __float_as_uint(Wc[(r0    ) * LDWM + ks * 8 + tg]);
                Af[mt][1] = __float_as_uint(Wc[(r0 + 8) * LDWM + ks * 8 + tg]);
                Af[mt][2] = __float_as_uint(Wc[(r0    ) * LDWM + ks * 8 + tg + 4]);
                Af[mt][3] = __float_as_uint(Wc[(r0 + 8) * LDWM + ks * 8 + tg + 4]);
            }
            #pragma unroll
            for (int nt = 0; nt < 4; nt++) {
                uint32_t b0 = f2tf(Xc[(ks * 8 + tg    ) * LDXM + wn + nt * 8 + g]);
                uint32_t b1 = f2tf(Xc[(ks * 8 + tg + 4) * LDXM + wn + nt * 8 + g]);
                #pragma unroll
                for (int mt = 0; mt < 4; mt++)
                    mma8(acc[mt][nt], Af[mt], b0, b1);
            }
        }
        __syncthreads();
    }

    // epilogue
    #pragma unroll
    for (int mt = 0; mt < 4; mt++) {
        int o_g  = o0 + wo + mt * 16 + g;
        int o_g8 = o_g + 8;
        float bg  = bias[o_g];
        float bg8 = bias[o_g8];
        #pragma unroll
        for (int nt = 0; nt < 4; nt++) {
            int n = n0 + wn + nt * 8 + 2 * tg;
            float c0 = acc[mt][nt][0] + bg,  c1 = acc[mt][nt][1] + bg;
            float c2 = acc[mt][nt][2] + bg8, c3 = acc[mt][nt][3] + bg8;
            if (mode == 0) {
                *reinterpret_cast<float2*>(out + ((size_t)b * OC + o_g ) * N + n) =
                    make_float2(c0, c1);
                *reinterpret_cast<float2*>(out + ((size_t)b * OC + o_g8) * N + n) =
                    make_float2(c2, c3);
            } else {
                c0 = __uint_as_float(f2tf(c0 * oscale));
                c1 = __uint_as_float(f2tf(c1 * oscale));
                c2 = __uint_as_float(f2tf(c2 * oscale));
                c3 = __uint_as_float(f2tf(c3 * oscale));
                int h0 = o_g & 3,  d0 = o_g >> 2;
                int h1 = o_g8 & 3, d1 = o_g8 >> 2;
                out[(((size_t)b * HH + h0) * N + n    ) * 64 + d0] = c0;
                out[(((size_t)b * HH + h0) * N + n + 1) * 64 + d0] = c1;
                out[(((size_t)b * HH + h1) * N + n    ) * 64 + d1] = c2;
                out[(((size_t)b * HH + h1) * N + n + 1) * 64 + d1] = c3;
            }
        }
    }
}

// ---------------------------------------------------------------------------
// InstanceNorm1d (affine=False, biased var) + ReLU, in place.
// ---------------------------------------------------------------------------
__global__ void instnorm_relu(float* __restrict__ hb, int N)
{
    int row = blockIdx.x;
    float* p = hb + (size_t)row * N;

    float s = 0.f, s2 = 0.f;
    for (int i = threadIdx.x; i < N; i += blockDim.x) {
        float v = p[i];
        s  += v;
        s2 = fmaf(v, v, s2);
    }
    #pragma unroll
    for (int off = 16; off > 0; off >>= 1) {
        s  += __shfl_xor_sync(0xffffffffu, s,  off);
        s2 += __shfl_xor_sync(0xffffffffu, s2, off);
    }
    __shared__ float sh[16];
    int wid = threadIdx.x >> 5, lid = threadIdx.x & 31;
    if (lid == 0) { sh[wid] = s; sh[wid + 8] = s2; }
    __syncthreads();
    if (threadIdx.x < 32) {
        s  = (lid < 8) ? sh[lid]     : 0.f;
        s2 = (lid < 8) ? sh[lid + 8] : 0.f;
        #pragma unroll
        for (int off = 4; off > 0; off >>= 1) {
            s  += __shfl_xor_sync(0xffffffffu, s,  off);
            s2 += __shfl_xor_sync(0xffffffffu, s2, off);
        }
        if (lid == 0) { sh[0] = s; sh[1] = s2; }
    }
    __syncthreads();
    float mean = sh[0] / (float)N;
    float var  = sh[1] / (float)N - mean * mean;
    float inv  = rsqrtf(var + 1e-5f);
    for (int i = threadIdx.x; i < N; i += blockDim.x)
        p[i] = fmaxf(0.f, (p[i] - mean) * inv);
}

// ---------------------------------------------------------------------------
extern "C" void kernel_launch(void* const* d_in, const int* in_sizes, int n_in,
                              void* d_out, int out_size)
{
    const float* x   = (const float*)d_in[0];
    const float* src = (const float*)d_in[1];
    const float* Wq  = (const float*)d_in[2];
    const float* bq  = (const float*)d_in[3];
    const float* Wk  = (const float*)d_in[4];
    const float* bk  = (const float*)d_in[5];
    const float* Wv  = (const float*)d_in[6];
    const float* bv  = (const float*)d_in[7];
    const float* Wm  = (const float*)d_in[8];
    const float* bm  = (const float*)d_in[9];
    const float* W1  = (const float*)d_in[10];
    const float* b1  = (const float*)d_in[11];
    const float* W2  = (const float*)d_in[12];
    const float* b2  = (const float*)d_in[13];

    const int B = BB, D = DD;
    const int N = in_sizes[0] / (B * D);
    const int M = in_sizes[1] / (B * D);

    float *qp, *kp, *vp, *attnp, *msgp, *hp, *wts;
    cudaGetSymbolAddress((void**)&qp,    g_q);
    cudaGetSymbolAddress((void**)&kp,    g_k);
    cudaGetSymbolAddress((void**)&vp,    g_v);
    cudaGetSymbolAddress((void**)&attnp, g_attn);
    cudaGetSymbolAddress((void**)&msgp,  g_msg);
    cudaGetSymbolAddress((void**)&hp,    g_h);
    cudaGetSymbolAddress((void**)&wts,   g_wts);

    const int gsmem = (2 * 128 * LDWM + 2 * 32 * LDXM) * (int)sizeof(float);
    const int fsmem = (2 * 64 * LDK + 2 * 64 * LDV + 128 * LDP) * (int)sizeof(float);
    cudaFuncSetAttribute(gemm_tc, cudaFuncAttributeMaxDynamicSharedMemorySize, gsmem);
    cudaFuncSetAttribute(flash_attn_tc, cudaFuncAttributeMaxDynamicSharedMemorySize, fsmem);

    // 0. round weights to tf32
    round_weights<<<(655360 + 255) / 256, 256>>>(Wq, Wk, Wv, Wm, W1, W2, wts);

    const float QSCALE = 0.125f * 1.44269504088896340736f;  // 1/sqrt(64) * log2(e)

    // 1. Q/K/V projections (head-permuted, tf32-rounded outputs)
    gemm_tc<<<dim3(N / 128, D / 128, B), 256, gsmem>>>(wts + OFF_WQ, bq, x,   D, nullptr, qp, D, D, N, 1, QSCALE);
    gemm_tc<<<dim3(M / 128, D / 128, B), 256, gsmem>>>(wts + OFF_WK, bk, src, D, nullptr, kp, D, D, M, 1, 1.0f);
    gemm_tc<<<dim3(M / 128, D / 128, B), 256, gsmem>>>(wts + OFF_WV, bv, src, D, nullptr, vp, D, D, M, 1, 1.0f);

    // 2. fused tf32 mma attention
    flash_attn_tc<<<dim3(N / 128, HH, B), 256, fsmem>>>(qp, kp, vp, attnp, N, M);

    // 3. message projection
    gemm_tc<<<dim3(N / 128, D / 128, B), 256, gsmem>>>(wts + OFF_WM, bm, attnp, D, nullptr, msgp, D, D, N, 0, 1.0f);

    // 4. MLP first layer on virtual concat [x; message]
    gemm_tc<<<dim3(N / 128, (2 * D) / 128, B), 256, gsmem>>>(wts + OFF_W1, b1, x, D, msgp, hp, 2 * D, 2 * D, N, 0, 1.0f);

    // 5. InstanceNorm + ReLU
    instnorm_relu<<<B * 2 * D, 256>>>(hp, N);

    // 6. final projection -> d_out
    gemm_tc<<<dim3(N / 128, D / 128, B), 256, gsmem>>>(wts + OFF_W2, b2, hp, 2 * D, nullptr, (float*)d_out, D, 2 * D, N, 0, 1.0f);
}

// round 5
// speedup vs baseline: 1.1148x; 1.1148x over previous
#include <cuda_runtime.h>
#include <cstdint>
#include <cstddef>

// ---------------------------------------------------------------------------
// AttentionalPropagation, B=2, D=256, H=4, dim=64, N=M=4096.
// R5: flash = 4 warps x 32 q-rows (min crossbar/row), 108.5KB smem (2 CTA/SM),
//     raw-bit tf32 fragments + ex2 softmax; fused QKV projection launch.
// ---------------------------------------------------------------------------

#define BB 2
#define DD 256
#define HH 4

__device__ float g_q   [BB * HH * 4096 * 64];   // [b][h][n][di] (tf32, pre-scaled)
__device__ float g_k   [BB * HH * 4096 * 64];   // [b][h][m][di] (tf32)
__device__ float g_v   [BB * HH * 4096 * 64];   // [b][h][m][di] (tf32)
__device__ float g_attn[BB * DD * 4096];        // (B, D, N)
__device__ float g_msg [BB * DD * 4096];
__device__ float g_h   [BB * 2 * DD * 4096];    // (B, 2D, N)
__device__ float g_wts [655360];                // tf32-rounded weights

#define OFF_WQ 0
#define OFF_WK 65536
#define OFF_WV 131072
#define OFF_WM 196608
#define OFF_W1 262144
#define OFF_W2 524288

#define QSCALE (0.125f * 1.44269504088896340736f)   // 1/sqrt(64) * log2(e)

// ============================ PTX helpers ==================================
__device__ __forceinline__ uint32_t smem_u32(const void* p) {
    uint32_t a;
    asm("{ .reg .u64 t; cvta.to.shared.u64 t, %1; cvt.u32.u64 %0, t; }"
        : "=r"(a) : "l"(p));
    return a;
}
__device__ __forceinline__ uint32_t f2tf(float x) {
    uint32_t r; asm("cvt.rna.tf32.f32 %0, %1;" : "=r"(r) : "f"(x)); return r;
}
__device__ __forceinline__ float ex2(float x) {
    float r; asm("ex2.approx.f32 %0, %1;" : "=f"(r) : "f"(x)); return r;
}
__device__ __forceinline__ void mma8(float* d, const uint32_t* a,
                                     uint32_t b0, uint32_t b1) {
    asm volatile("mma.sync.aligned.m16n8k8.row.col.f32.tf32.tf32.f32 "
        "{%0,%1,%2,%3}, {%4,%5,%6,%7}, {%8,%9}, {%0,%1,%2,%3};"
        : "+f"(d[0]), "+f"(d[1]), "+f"(d[2]), "+f"(d[3])
        : "r"(a[0]), "r"(a[1]), "r"(a[2]), "r"(a[3]), "r"(b0), "r"(b1));
}
__device__ __forceinline__ void cp16(uint32_t s, const void* g) {
    asm volatile("cp.async.ca.shared.global [%0], [%1], 16;" :: "r"(s), "l"(g));
}
#define CP_COMMIT() asm volatile("cp.async.commit_group;" ::: "memory")
#define CP_WAIT(n)  asm volatile("cp.async.wait_group %0;" :: "n"(n) : "memory")

// ---------------------------------------------------------------------------
// round weights to tf32 once (deterministic)
// ---------------------------------------------------------------------------
__global__ void round_weights(const float* __restrict__ wq, const float* __restrict__ wk,
                              const float* __restrict__ wv, const float* __restrict__ wm,
                              const float* __restrict__ w1, const float* __restrict__ w2,
                              float* __restrict__ dst)
{
    int i = blockIdx.x * 256 + threadIdx.x;
    if (i >= 655360) return;
    float v;
    if      (i < OFF_WK) v = wq[i - OFF_WQ];
    else if (i < OFF_WV) v = wk[i - OFF_WK];
    else if (i < OFF_WM) v = wv[i - OFF_WV];
    else if (i < OFF_W1) v = wm[i - OFF_WM];
    else if (i < OFF_W2) v = w1[i - OFF_W1];
    else                 v = w2[i - OFF_W2];
    dst[i] = __uint_as_float(f2tf(v));
}

// ---------------------------------------------------------------------------
// tf32 mma flash attention. grid (N/128, H, B), 128 threads (4 warps),
// 32 q-rows per warp (2 m16 tiles) -> minimal K/V crossbar traffic per row.
// Q/K/V pre-rounded tf32; Q pre-scaled by 0.125*log2(e) -> ex2 softmax.
// smem 108.5KB -> 2 CTAs/SM.
// ---------------------------------------------------------------------------
#define LDK 68
#define LDV 68
#define LDP 76
#define LDT 132

__global__ void __launch_bounds__(128)
flash_attn_tc(const float* __restrict__ q, const float* __restrict__ k,
              const float* __restrict__ v, float* __restrict__ attn,
              int N, int M)
{
    extern __shared__ float sm[];
    float* Ks = sm;                              // [2][64][LDK]
    float* Vs = sm + 2 * 64 * LDK;               // [2][64][LDV]
    float* Ps = sm + 2 * 64 * LDK + 2 * 64 * LDV;// [128][LDP] (Q stage / P / O^T)

    const int b  = blockIdx.z, h = blockIdx.y;
    const int n0 = blockIdx.x * 128;
    const int bh = b * HH + h;
    const int t  = threadIdx.x;
    const int wid = t >> 5, lane = t & 31;
    const int g = lane >> 2, tg = lane & 3;
    const int wr = wid * 32;

    const float* Kg = k + (size_t)bh * M * 64;
    const float* Vg = v + (size_t)bh * M * 64;

    // prefetch K/V tile 0
    {
        uint32_t kd = smem_u32(Ks), vd = smem_u32(Vs);
        #pragma unroll
        for (int i = 0; i < 8; i++) {
            int idx = t + i * 128;
            int r = idx >> 4, c = (idx & 15) * 4;
            cp16(kd + (uint32_t)(r * LDK + c) * 4, Kg + r * 64 + c);
            cp16(vd + (uint32_t)(r * LDV + c) * 4, Vg + r * 64 + c);
        }
        CP_COMMIT();
    }

    // stage Q into Ps (raw: already scaled + tf32-rounded)
    {
        const float* Qg = q + ((size_t)bh * N + n0) * 64;
        #pragma unroll
        for (int i = 0; i < 16; i++) {
            int idx = t + i * 128;
            int r = idx >> 4, c = (idx & 15) * 4;
            *reinterpret_cast<float4*>(Ps + r * LDP + c) =
                *reinterpret_cast<const float4*>(Qg + r * 64 + c);
        }
    }
    __syncthreads();

    // persistent Q fragments (raw bits)
    uint32_t Qf[2][8][4];
    #pragma unroll
    for (int mt = 0; mt < 2; mt++) {
        int r0 = wr + mt * 16 + g;
        #pragma unroll
        for (int kk = 0; kk < 8; kk++) {
            Qf[mt][kk][0] = __float_as_uint(Ps[(r0    ) * LDP + kk * 8 + tg]);
            Qf[mt][kk][1] = __float_as_uint(Ps[(r0 + 8) * LDP + kk * 8 + tg]);
            Qf[mt][kk][2] = __float_as_uint(Ps[(r0    ) * LDP + kk * 8 + tg + 4]);
            Qf[mt][kk][3] = __float_as_uint(Ps[(r0 + 8) * LDP + kk * 8 + tg + 4]);
        }
    }
    __syncthreads();

    float Of[8][2][4] = {};
    float lrow[2][2]  = {};

    const int nT = M / 64;
    for (int tt = 0; tt < nT; tt++) {
        const float* Kc = Ks + (tt & 1) * 64 * LDK;
        const float* Vc = Vs + (tt & 1) * 64 * LDV;

        if (tt + 1 < nT) {
            uint32_t kd = smem_u32(Ks + ((tt + 1) & 1) * 64 * LDK);
            uint32_t vd = smem_u32(Vs + ((tt + 1) & 1) * 64 * LDV);
            const float* Kn = Kg + (size_t)(tt + 1) * 64 * 64;
            const float* Vn = Vg + (size_t)(tt + 1) * 64 * 64;
            #pragma unroll
            for (int i = 0; i < 8; i++) {
                int idx = t + i * 128;
                int r = idx >> 4, c = (idx & 15) * 4;
                cp16(kd + (uint32_t)(r * LDK + c) * 4, Kn + r * 64 + c);
                cp16(vd + (uint32_t)(r * LDV + c) * 4, Vn + r * 64 + c);
            }
            CP_COMMIT();
            CP_WAIT(1);
        } else {
            CP_WAIT(0);
        }
        __syncthreads();

        // S = Q K^T (raw-bit fragments)
        float Sc[8][2][4] = {};
        #pragma unroll
        for (int j = 0; j < 8; j++) {
            const float* Kr = Kc + (j * 8 + g) * LDK + tg;
            #pragma unroll
            for (int kk = 0; kk < 8; kk++) {
                uint32_t b0 = __float_as_uint(Kr[kk * 8]);
                uint32_t b1 = __float_as_uint(Kr[kk * 8 + 4]);
                mma8(Sc[j][0], Qf[0][kk], b0, b1);
                mma8(Sc[j][1], Qf[1][kk], b0, b1);
            }
        }

        // exp2 + row-sum + store P (tf32-rounded); rows warp-private
        #pragma unroll
        for (int mt = 0; mt < 2; mt++) {
            int r0 = wr + mt * 16 + g;
            #pragma unroll
            for (int j = 0; j < 8; j++) {
                float e0 = ex2(Sc[j][mt][0]);
                float e1 = ex2(Sc[j][mt][1]);
                float e2 = ex2(Sc[j][mt][2]);
                float e3 = ex2(Sc[j][mt][3]);
                lrow[mt][0] += e0 + e1;
                lrow[mt][1] += e2 + e3;
                *reinterpret_cast<float2*>(Ps + (r0    ) * LDP + j * 8 + 2 * tg) =
                    make_float2(__uint_as_float(f2tf(e0)), __uint_as_float(f2tf(e1)));
                *reinterpret_cast<float2*>(Ps + (r0 + 8) * LDP + j * 8 + 2 * tg) =
                    make_float2(__uint_as_float(f2tf(e2)), __uint_as_float(f2tf(e3)));
            }
        }

        // O += P V
        #pragma unroll
        for (int kk = 0; kk < 8; kk++) {
            uint32_t Pa[2][4];
            #pragma unroll
            for (int mt = 0; mt < 2; mt++) {
                int r0 = wr + mt * 16 + g;
                Pa[mt][0] = __float_as_uint(Ps[(r0    ) * LDP + kk * 8 + tg]);
                Pa[mt][1] = __float_as_uint(Ps[(r0 + 8) * LDP + kk * 8 + tg]);
                Pa[mt][2] = __float_as_uint(Ps[(r0    ) * LDP + kk * 8 + tg + 4]);
                Pa[mt][3] = __float_as_uint(Ps[(r0 + 8) * LDP + kk * 8 + tg + 4]);
            }
            const float* Vr0 = Vc + (kk * 8 + tg    ) * LDV + g;
            const float* Vr1 = Vc + (kk * 8 + tg + 4) * LDV + g;
            #pragma unroll
            for (int j = 0; j < 8; j++) {
                uint32_t b0 = __float_as_uint(Vr0[j * 8]);
                uint32_t b1 = __float_as_uint(Vr1[j * 8]);
                mma8(Of[j][0], Pa[0], b0, b1);
                mma8(Of[j][1], Pa[1], b0, b1);
            }
        }
        __syncthreads();
    }

    // finalize l across the 4-lane column group
    #pragma unroll
    for (int mt = 0; mt < 2; mt++)
        #pragma unroll
        for (int r = 0; r < 2; r++) {
            float s = lrow[mt][r];
            s += __shfl_xor_sync(0xffffffffu, s, 1);
            s += __shfl_xor_sync(0xffffffffu, s, 2);
            lrow[mt][r] = 1.0f / s;
        }

    __syncthreads();
    // stage O transposed: Pt[di][n_local]
    float* Pt = Ps;
    #pragma unroll
    for (int j = 0; j < 8; j++) {
        #pragma unroll
        for (int mt = 0; mt < 2; mt++) {
            int r0 = wr + mt * 16 + g;
            Pt[(j * 8 + 2 * tg    ) * LDT + r0    ] = Of[j][mt][0] * lrow[mt][0];
            Pt[(j * 8 + 2 * tg + 1) * LDT + r0    ] = Of[j][mt][1] * lrow[mt][0];
            Pt[(j * 8 + 2 * tg    ) * LDT + r0 + 8] = Of[j][mt][2] * lrow[mt][1];
            Pt[(j * 8 + 2 * tg + 1) * LDT + r0 + 8] = Of[j][mt][3] * lrow[mt][1];
        }
    }
    __syncthreads();

    // coalesced store into (B, D, N), channel = di*H + h
    #pragma unroll
    for (int cc = 0; cc < 16; cc++) {
        int di = wid * 16 + cc;
        float4 val = *reinterpret_cast<const float4*>(Pt + di * LDT + lane * 4);
        *reinterpret_cast<float4*>(
            attn + ((size_t)(b * DD + di * HH + h)) * N + n0 + lane * 4) = val;
    }
}

// ---------------------------------------------------------------------------
// Shared tf32 GEMM body (tile 128x128, BK=32, double-buffered cp.async,
// 8 warps, warp tile 64x32). W pre-rounded tf32 (raw-bit A fragments).
// ---------------------------------------------------------------------------
#define LDWM 36
#define LDXM 136

struct GemmOut {
    float acc[4][4][4];
    int o0, n0, wo, wn, g, tg;
};

__device__ __forceinline__ void gemm_body(
    const float* __restrict__ W, const float* __restrict__ X0, int C0,
    const float* __restrict__ X1, int b, int IC, int N,
    int o0, int n0, float* sm, GemmOut& R)
{
    float* Ws = sm;
    float* Xs = sm + 2 * 128 * LDWM;

    const int t  = threadIdx.x;
    const int wid = t >> 5, lane = t & 31;
    R.g = lane >> 2; R.tg = lane & 3;
    R.wo = (wid & 1) * 64;
    R.wn = (wid >> 1) * 32;
    R.o0 = o0; R.n0 = n0;

    auto stage = [&](int buf, int k0) {
        uint32_t wd = smem_u32(Ws + buf * 128 * LDWM);
        uint32_t xd = smem_u32(Xs + buf * 32 * LDXM);
        #pragma unroll
        for (int i = 0; i < 4; i++) {
            int idx = t + i * 256;
            int r = idx >> 3, c = (idx & 7) * 4;
            cp16(wd + (uint32_t)(r * LDWM + c) * 4,
                 W + (size_t)(o0 + r) * IC + k0 + c);
        }
        #pragma unroll
        for (int i = 0; i < 4; i++) {
            int idx = t + i * 256;
            int r = idx >> 5, c = (idx & 31) * 4;
            int ch = k0 + r;
            const float* src = (ch < C0)
                ? (X0 + ((size_t)b * C0 + ch) * N)
                : (X1 + ((size_t)b * (IC - C0) + (ch - C0)) * N);
            cp16(xd + (uint32_t)(r * LDXM + c) * 4, src + n0 + c);
        }
        CP_COMMIT();
    };

    stage(0, 0);
    #pragma unroll
    for (int a = 0; a < 4; a++)
        #pragma unroll
        for (int c = 0; c < 4; c++)
            #pragma unroll
            for (int d = 0; d < 4; d++) R.acc[a][c][d] = 0.f;

    const int nK = IC / 32;
    for (int kt = 0; kt < nK; kt++) {
        if (kt + 1 < nK) { stage((kt + 1) & 1, (kt + 1) * 32); CP_WAIT(1); }
        else             { CP_WAIT(0); }
        __syncthreads();
        const float* Wc = Ws + (kt & 1) * 128 * LDWM;
        const float* Xc = Xs + (kt & 1) * 32 * LDXM;

        #pragma unroll
        for (int ks = 0; ks < 4; ks++) {
            uint32_t Af[4][4];
            #pragma unroll
            for (int mt = 0; mt < 4; mt++) {
                int r0 = R.wo + mt * 16 + R.g;
                Af[mt][0] = __float_as_uint(Wc[(r0    ) * LDWM + ks * 8 + R.tg]);
                Af[mt][1] = __float_as_uint(Wc[(r0 + 8) * LDWM + ks * 8 + R.tg]);
                Af[mt][2] = __float_as_uint(Wc[(r0    ) * LDWM + ks * 8 + R.tg + 4]);
                Af[mt][3] = __float_as_uint(Wc[(r0 + 8) * LDWM + ks * 8 + R.tg + 4]);
            }
            #pragma unroll
            for (int nt = 0; nt < 4; nt++) {
                uint32_t b0 = f2tf(Xc[(ks * 8 + R.tg    ) * LDXM + R.wn + nt * 8 + R.g]);
                uint32_t b1 = f2tf(Xc[(ks * 8 + R.tg + 4) * LDXM + R.wn + nt * 8 + R.g]);
                #pragma unroll
                for (int mt = 0; mt < 4; mt++)
                    mma8(R.acc[mt][nt], Af[mt], b0, b1);
            }
        }
        __syncthreads();
    }
}

// generic projection: mode 0 (B,OC,N) layout
__global__ void __launch_bounds__(256)
gemm_tc(const float* __restrict__ W, const float* __restrict__ bias,
        const float* __restrict__ X0, int C0, const float* __restrict__ X1,
        float* __restrict__ out, int OC, int IC, int N)
{
    extern __shared__ float sm[];
    GemmOut R;
    gemm_body(W, X0, C0, X1, blockIdx.z, IC, N,
              blockIdx.y * 128, blockIdx.x * 128, sm, R);

    #pragma unroll
    for (int mt = 0; mt < 4; mt++) {
        int o_g  = R.o0 + R.wo + mt * 16 + R.g;
        int o_g8 = o_g + 8;
        float bg  = bias[o_g];
        float bg8 = bias[o_g8];
        #pragma unroll
        for (int nt = 0; nt < 4; nt++) {
            int n = R.n0 + R.wn + nt * 8 + 2 * R.tg;
            *reinterpret_cast<float2*>(out + ((size_t)blockIdx.z * OC + o_g ) * N + n) =
                make_float2(R.acc[mt][nt][0] + bg,  R.acc[mt][nt][1] + bg);
            *reinterpret_cast<float2*>(out + ((size_t)blockIdx.z * OC + o_g8) * N + n) =
                make_float2(R.acc[mt][nt][2] + bg8, R.acc[mt][nt][3] + bg8);
        }
    }
}

// fused Q/K/V projection: grid (N/128, 2, 6); z = which*2 + b.
// epilogue: head-permute [b][h][pos][di], scale, tf32-round.
__global__ void __launch_bounds__(256)
gemm_qkv(const float* __restrict__ wts,
         const float* __restrict__ bq, const float* __restrict__ bk,
         const float* __restrict__ bv,
         const float* __restrict__ x, const float* __restrict__ src,
         float* __restrict__ qp, float* __restrict__ kp, float* __restrict__ vp,
         int N)
{
    extern __shared__ float sm[];
    const int z = blockIdx.z;
    const int which = z >> 1;
    const int b = z & 1;
    const float* W    = wts + which * 65536;
    const float* bias = (which == 0) ? bq : (which == 1) ? bk : bv;
    const float* X    = (which == 0) ? x : src;
    float* out        = (which == 0) ? qp : (which == 1) ? kp : vp;
    const float oscale = (which == 0) ? QSCALE : 1.0f;

    GemmOut R;
    gemm_body(W, X, DD, nullptr, b, DD, N, blockIdx.y * 128, blockIdx.x * 128, sm, R);

    #pragma unroll
    for (int mt = 0; mt < 4; mt++) {
        int o_g  = R.o0 + R.wo + mt * 16 + R.g;
        int o_g8 = o_g + 8;
        float bg  = bias[o_g];
        float bg8 = bias[o_g8];
        #pragma unroll
        for (int nt = 0; nt < 4; nt++) {
            int n = R.n0 + R.wn + nt * 8 + 2 * R.tg;
            float c0 = __uint_as_float(f2tf((R.acc[mt][nt][0] + bg)  * oscale));
            float c1 = __uint_as_float(f2tf((R.acc[mt][nt][1] + bg)  * oscale));
            float c2 = __uint_as_float(f2tf((R.acc[mt][nt][2] + bg8) * oscale));
            float c3 = __uint_as_float(f2tf((R.acc[mt][nt][3] + bg8) * oscale));
            int h0 = o_g & 3,  d0 = o_g >> 2;
            int h1 = o_g8 & 3, d1 = o_g8 >> 2;
            out[(((size_t)b * HH + h0) * N + n    ) * 64 + d0] = c0;
            out[(((size_t)b * HH + h0) * N + n + 1) * 64 + d0] = c1;
            out[(((size_t)b * HH + h1) * N + n    ) * 64 + d1] = c2;
            out[(((size_t)b * HH + h1) * N + n + 1) * 64 + d1] = c3;
        }
    }
}

// ---------------------------------------------------------------------------
// InstanceNorm1d (affine=False, biased var) + ReLU, in place.
// ---------------------------------------------------------------------------
__global__ void instnorm_relu(float* __restrict__ hb, int N)
{
    int row = blockIdx.x;
    float* p = hb + (size_t)row * N;

    float s = 0.f, s2 = 0.f;
    for (int i = threadIdx.x; i < N; i += blockDim.x) {
        float v = p[i];
        s  += v;
        s2 = fmaf(v, v, s2);
    }
    #pragma unroll
    for (int off = 16; off > 0; off >>= 1) {
        s  += __shfl_xor_sync(0xffffffffu, s,  off);
        s2 += __shfl_xor_sync(0xffffffffu, s2, off);
    }
    __shared__ float sh[16];
    int wid = threadIdx.x >> 5, lid = threadIdx.x & 31;
    if (lid == 0) { sh[wid] = s; sh[wid + 8] = s2; }
    __syncthreads();
    if (threadIdx.x < 32) {
        s  = (lid < 8) ? sh[lid]     : 0.f;
        s2 = (lid < 8) ? sh[lid + 8] : 0.f;
        #pragma unroll
        for (int off = 4; off > 0; off >>= 1) {
            s  += __shfl_xor_sync(0xffffffffu, s,  off);
            s2 += __shfl_xor_sync(0xffffffffu, s2, off);
        }
        if (lid == 0) { sh[0] = s; sh[1] = s2; }
    }
    __syncthreads();
    float mean = sh[0] / (float)N;
    float var  = sh[1] / (float)N - mean * mean;
    float inv  = rsqrtf(var + 1e-5f);
    for (int i = threadIdx.x; i < N; i += blockDim.x)
        p[i] = fmaxf(0.f, (p[i] - mean) * inv);
}

// ---------------------------------------------------------------------------
extern "C" void kernel_launch(void* const* d_in, const int* in_sizes, int n_in,
                              void* d_out, int out_size)
{
    const float* x   = (const float*)d_in[0];
    const float* src = (const float*)d_in[1];
    const float* Wq  = (const float*)d_in[2];
    const float* bq  = (const float*)d_in[3];
    const float* Wk  = (const float*)d_in[4];
    const float* bk  = (const float*)d_in[5];
    const float* Wv  = (const float*)d_in[6];
    const float* bv  = (const float*)d_in[7];
    const float* Wm  = (const float*)d_in[8];
    const float* bm  = (const float*)d_in[9];
    const float* W1  = (const float*)d_in[10];
    const float* b1  = (const float*)d_in[11];
    const float* W2  = (const float*)d_in[12];
    const float* b2  = (const float*)d_in[13];

    const int B = BB, D = DD;
    const int N = in_sizes[0] / (B * D);
    const int M = in_sizes[1] / (B * D);
    (void)M;

    float *qp, *kp, *vp, *attnp, *msgp, *hp, *wts;
    cudaGetSymbolAddress((void**)&qp,    g_q);
    cudaGetSymbolAddress((void**)&kp,    g_k);
    cudaGetSymbolAddress((void**)&vp,    g_v);
    cudaGetSymbolAddress((void**)&attnp, g_attn);
    cudaGetSymbolAddress((void**)&msgp,  g_msg);
    cudaGetSymbolAddress((void**)&hp,    g_h);
    cudaGetSymbolAddress((void**)&wts,   g_wts);

    const int gsmem = (2 * 128 * LDWM + 2 * 32 * LDXM) * (int)sizeof(float);      // 71680
    const int fsmem = (2 * 64 * LDK + 2 * 64 * LDV + 128 * LDP) * (int)sizeof(float); // 108544
    cudaFuncSetAttribute(gemm_tc,  cudaFuncAttributeMaxDynamicSharedMemorySize, gsmem);
    cudaFuncSetAttribute(gemm_qkv, cudaFuncAttributeMaxDynamicSharedMemorySize, gsmem);
    cudaFuncSetAttribute(flash_attn_tc, cudaFuncAttributeMaxDynamicSharedMemorySize, fsmem);

    // 0. round weights to tf32
    round_weights<<<(655360 + 255) / 256, 256>>>(Wq, Wk, Wv, Wm, W1, W2, wts);

    // 1. fused Q/K/V projections (head-permuted, tf32-rounded, Q pre-scaled)
    gemm_qkv<<<dim3(N / 128, D / 128, 3 * B), 256, gsmem>>>(
        wts, bq, bk, bv, x, src, qp, kp, vp, N);

    // 2. fused tf32 mma attention
    flash_attn_tc<<<dim3(N / 128, HH, B), 128, fsmem>>>(qp, kp, vp, attnp, N, M);

    // 3. message projection
    gemm_tc<<<dim3(N / 128, D / 128, B), 256, gsmem>>>(
        wts + OFF_WM, bm, attnp, D, nullptr, msgp, D, D, N);

    // 4. MLP first layer on virtual concat [x; message]
    gemm_tc<<<dim3(N / 128, (2 * D) / 128, B), 256, gsmem>>>(
        wts + OFF_W1, b1, x, D, msgp, hp, 2 * D, 2 * D, N);

    // 5. InstanceNorm + ReLU
    instnorm_relu<<<B * 2 * D, 256>>>(hp, N);

    // 6. final projection -> d_out
    gemm_tc<<<dim3(N / 128, D / 128, B), 256, gsmem>>>(
        wts + OFF_W2, b2, hp, 2 * D, nullptr, (float*)d_out, D, 2 * D, N);
}

// round 6
// speedup vs baseline: 1.6858x; 1.5122x over previous
#include <cuda_runtime.h>
#include <cuda_bf16.h>
#include <cstdint>
#include <cstddef>

// ---------------------------------------------------------------------------
// AttentionalPropagation, B=2, D=256, H=4, dim=64, N=M=4096.
// R6: flash attention in bf16 mma.m16n8k16 (halved crossbar bytes + mma count);
//     projections stay tf32 mma (precision). 4 warps x 32 q-rows, 54KB smem.
// ---------------------------------------------------------------------------

#define BB 2
#define DD 256
#define HH 4

__device__ __nv_bfloat16 g_q[BB * HH * 4096 * 64];  // [b][h][n][di], pre-scaled
__device__ __nv_bfloat16 g_k[BB * HH * 4096 * 64];  // [b][h][m][di]
__device__ __nv_bfloat16 g_v[BB * HH * 64 * 4096];  // [b][h][di][m] (transposed)
__device__ float g_attn[BB * DD * 4096];            // (B, D, N)
__device__ float g_msg [BB * DD * 4096];
__device__ float g_h   [BB * 2 * DD * 4096];        // (B, 2D, N)
__device__ float g_wts [655360];                    // tf32-rounded weights

#define OFF_WQ 0
#define OFF_WK 65536
#define OFF_WV 131072
#define OFF_WM 196608
#define OFF_W1 262144
#define OFF_W2 524288

#define QSCALE (0.125f * 1.44269504088896340736f)   // 1/sqrt(64) * log2(e)

// ============================ PTX helpers ==================================
__device__ __forceinline__ uint32_t smem_u32(const void* p) {
    uint32_t a;
    asm("{ .reg .u64 t; cvta.to.shared.u64 t, %1; cvt.u32.u64 %0, t; }"
        : "=r"(a) : "l"(p));
    return a;
}
__device__ __forceinline__ uint32_t f2tf(float x) {
    uint32_t r; asm("cvt.rna.tf32.f32 %0, %1;" : "=r"(r) : "f"(x)); return r;
}
__device__ __forceinline__ float ex2(float x) {
    float r; asm("ex2.approx.f32 %0, %1;" : "=f"(r) : "f"(x)); return r;
}
__device__ __forceinline__ uint32_t packbf(float lo, float hi) {
    __nv_bfloat162 h = __floats2bfloat162_rn(lo, hi);   // .x = lo, .y = hi
    return *reinterpret_cast<uint32_t*>(&h);
}
// tf32 m16n8k8
__device__ __forceinline__ void mma8(float* d, const uint32_t* a,
                                     uint32_t b0, uint32_t b1) {
    asm volatile("mma.sync.aligned.m16n8k8.row.col.f32.tf32.tf32.f32 "
        "{%0,%1,%2,%3}, {%4,%5,%6,%7}, {%8,%9}, {%0,%1,%2,%3};"
        : "+f"(d[0]), "+f"(d[1]), "+f"(d[2]), "+f"(d[3])
        : "r"(a[0]), "r"(a[1]), "r"(a[2]), "r"(a[3]), "r"(b0), "r"(b1));
}
// bf16 m16n8k16
__device__ __forceinline__ void mma16(float* d, const uint32_t* a,
                                      uint32_t b0, uint32_t b1) {
    asm volatile("mma.sync.aligned.m16n8k16.row.col.f32.bf16.bf16.f32 "
        "{%0,%1,%2,%3}, {%4,%5,%6,%7}, {%8,%9}, {%0,%1,%2,%3};"
        : "+f"(d[0]), "+f"(d[1]), "+f"(d[2]), "+f"(d[3])
        : "r"(a[0]), "r"(a[1]), "r"(a[2]), "r"(a[3]), "r"(b0), "r"(b1));
}
__device__ __forceinline__ void cp16(uint32_t s, const void* g) {
    asm volatile("cp.async.ca.shared.global [%0], [%1], 16;" :: "r"(s), "l"(g));
}
#define CP_COMMIT() asm volatile("cp.async.commit_group;" ::: "memory")
#define CP_WAIT(n)  asm volatile("cp.async.wait_group %0;" :: "n"(n) : "memory")

// ---------------------------------------------------------------------------
// round weights to tf32 once (deterministic)
// ---------------------------------------------------------------------------
__global__ void round_weights(const float* __restrict__ wq, const float* __restrict__ wk,
                              const float* __restrict__ wv, const float* __restrict__ wm,
                              const float* __restrict__ w1, const float* __restrict__ w2,
                              float* __restrict__ dst)
{
    int i = blockIdx.x * 256 + threadIdx.x;
    if (i >= 655360) return;
    float v;
    if      (i < OFF_WK) v = wq[i - OFF_WQ];
    else if (i < OFF_WV) v = wk[i - OFF_WK];
    else if (i < OFF_WM) v = wv[i - OFF_WV];
    else if (i < OFF_W1) v = wm[i - OFF_WM];
    else if (i < OFF_W2) v = w1[i - OFF_W1];
    else                 v = w2[i - OFF_W2];
    dst[i] = __uint_as_float(f2tf(v));
}

// ---------------------------------------------------------------------------
// bf16 flash attention. grid (N/128, H, B), 128 threads (4 warps),
// 32 q-rows per warp. K smem [m][di], V smem [di][m] (gmem pre-transposed),
// P packed bf16x2. All smem pitches 72 bf16 (36 words): banks = 4g+tg, clean.
// smem 54KB -> 2 CTAs/SM (reg-limited anyway). ex2 softmax, no-max.
// ---------------------------------------------------------------------------
#define LDB 72          // bf16 pitch for K / V / Q / P tiles
#define LDT 132         // fp32 pitch for O^T staging

__global__ void __launch_bounds__(128)
flash_attn_bf(const __nv_bfloat16* __restrict__ q, const __nv_bfloat16* __restrict__ k,
              const __nv_bfloat16* __restrict__ v, float* __restrict__ attn,
              int N, int M)
{
    extern __shared__ char smb[];
    __nv_bfloat16* Ks = reinterpret_cast<__nv_bfloat16*>(smb);            // [2][64][LDB]
    __nv_bfloat16* Vs = reinterpret_cast<__nv_bfloat16*>(smb + 18432);    // [2][64][LDB]
    __nv_bfloat16* Qs = reinterpret_cast<__nv_bfloat16*>(smb + 36864);    // [128][LDB] (Q then P)
    float* OT = reinterpret_cast<float*>(smb);                            // [64][LDT] epilogue

    const int b  = blockIdx.z, h = blockIdx.y;
    const int n0 = blockIdx.x * 128;
    const int bh = b * HH + h;
    const int t  = threadIdx.x;
    const int wid = t >> 5, lane = t & 31;
    const int g = lane >> 2, tg = lane & 3;
    const int wr = wid * 32;

    const __nv_bfloat16* Kg = k + (size_t)bh * M * 64;
    const __nv_bfloat16* Vg = v + (size_t)bh * 64 * M;

    // prefetch K/V tile 0: 64 rows x 128B each, 8x16B chunks/row
    {
        uint32_t kd = smem_u32(Ks), vd = smem_u32(Vs);
        #pragma unroll
        for (int i = 0; i < 4; i++) {
            int idx = t + i * 128;
            int r = idx >> 3, c = (idx & 7) * 8;
            cp16(kd + (uint32_t)(r * LDB + c) * 2, Kg + r * 64 + c);
            cp16(vd + (uint32_t)(r * LDB + c) * 2, Vg + (size_t)r * M + c);
        }
        CP_COMMIT();
    }

    // stage Q (pre-scaled, bf16) into Qs
    {
        const __nv_bfloat16* Qg = q + ((size_t)bh * N + n0) * 64;
        #pragma unroll
        for (int i = 0; i < 8; i++) {
            int idx = t + i * 128;
            int r = idx >> 3, c = (idx & 7) * 8;
            *reinterpret_cast<uint4*>(Qs + r * LDB + c) =
                *reinterpret_cast<const uint4*>(Qg + r * 64 + c);
        }
    }
    __syncthreads();

    // persistent Q fragments: [m-tile][k-step 0..3][4 regs], each reg = bf16 pair
    uint32_t Qf[2][4][4];
    #pragma unroll
    for (int mt = 0; mt < 2; mt++) {
        int r0 = wr + mt * 16 + g;
        #pragma unroll
        for (int kk = 0; kk < 4; kk++) {
            Qf[mt][kk][0] = *reinterpret_cast<uint32_t*>(Qs + (r0    ) * LDB + kk * 16 + 2 * tg);
            Qf[mt][kk][1] = *reinterpret_cast<uint32_t*>(Qs + (r0 + 8) * LDB + kk * 16 + 2 * tg);
            Qf[mt][kk][2] = *reinterpret_cast<uint32_t*>(Qs + (r0    ) * LDB + kk * 16 + 2 * tg + 8);
            Qf[mt][kk][3] = *reinterpret_cast<uint32_t*>(Qs + (r0 + 8) * LDB + kk * 16 + 2 * tg + 8);
        }
    }
    __syncthreads();

    __nv_bfloat16* Ps = Qs;    // reuse Q region for P
    float Of[8][2][4] = {};
    float lrow[2][2]  = {};

    const int nT = M / 64;
    for (int tt = 0; tt < nT; tt++) {
        const __nv_bfloat16* Kc = Ks + (tt & 1) * 64 * LDB;
        const __nv_bfloat16* Vc = Vs + (tt & 1) * 64 * LDB;

        if (tt + 1 < nT) {
            uint32_t kd = smem_u32(Ks + ((tt + 1) & 1) * 64 * LDB);
            uint32_t vd = smem_u32(Vs + ((tt + 1) & 1) * 64 * LDB);
            const __nv_bfloat16* Kn = Kg + (size_t)(tt + 1) * 64 * 64;
            const __nv_bfloat16* Vn = Vg + (size_t)(tt + 1) * 64;
            #pragma unroll
            for (int i = 0; i < 4; i++) {
                int idx = t + i * 128;
                int r = idx >> 3, c = (idx & 7) * 8;
                cp16(kd + (uint32_t)(r * LDB + c) * 2, Kn + r * 64 + c);
                cp16(vd + (uint32_t)(r * LDB + c) * 2, Vn + (size_t)r * M + c);
            }
            CP_COMMIT();
            CP_WAIT(1);
        } else {
            CP_WAIT(0);
        }
        __syncthreads();

        // S = Q K^T  (b-frags: bf16 pairs along di, contiguous)
        float Sc[8][2][4] = {};
        #pragma unroll
        for (int j = 0; j < 8; j++) {
            const __nv_bfloat16* Kr = Kc + (j * 8 + g) * LDB + 2 * tg;
            #pragma unroll
            for (int kk = 0; kk < 4; kk++) {
                uint32_t b0 = *reinterpret_cast<const uint32_t*>(Kr + kk * 16);
                uint32_t b1 = *reinterpret_cast<const uint32_t*>(Kr + kk * 16 + 8);
                mma16(Sc[j][0], Qf[0][kk], b0, b1);
                mma16(Sc[j][1], Qf[1][kk], b0, b1);
            }
        }

        // exp2 + row-sum + store P packed bf16x2 (rows warp-private, no sync)
        #pragma unroll
        for (int mt = 0; mt < 2; mt++) {
            int r0 = wr + mt * 16 + g;
            #pragma unroll
            for (int j = 0; j < 8; j++) {
                float e0 = ex2(Sc[j][mt][0]);
                float e1 = ex2(Sc[j][mt][1]);
                float e2 = ex2(Sc[j][mt][2]);
                float e3 = ex2(Sc[j][mt][3]);
                lrow[mt][0] += e0 + e1;
                lrow[mt][1] += e2 + e3;
                *reinterpret_cast<uint32_t*>(Ps + (r0    ) * LDB + j * 8 + 2 * tg) = packbf(e0, e1);
                *reinterpret_cast<uint32_t*>(Ps + (r0 + 8) * LDB + j * 8 + 2 * tg) = packbf(e2, e3);
            }
        }

        // O += P V   (V^T in smem: b-frag pairs along m, contiguous)
        #pragma unroll
        for (int kk = 0; kk < 4; kk++) {
            uint32_t Pa[2][4];
            #pragma unroll
            for (int mt = 0; mt < 2; mt++) {
                int r0 = wr + mt * 16 + g;
                Pa[mt][0] = *reinterpret_cast<uint32_t*>(Ps + (r0    ) * LDB + kk * 16 + 2 * tg);
                Pa[mt][1] = *reinterpret_cast<uint32_t*>(Ps + (r0 + 8) * LDB + kk * 16 + 2 * tg);
                Pa[mt][2] = *reinterpret_cast<uint32_t*>(Ps + (r0    ) * LDB + kk * 16 + 2 * tg + 8);
                Pa[mt][3] = *reinterpret_cast<uint32_t*>(Ps + (r0 + 8) * LDB + kk * 16 + 2 * tg + 8);
            }
            #pragma unroll
            for (int j = 0; j < 8; j++) {
                const __nv_bfloat16* Vr = Vc + (j * 8 + g) * LDB + kk * 16 + 2 * tg;
                uint32_t b0 = *reinterpret_cast<const uint32_t*>(Vr);
                uint32_t b1 = *reinterpret_cast<const uint32_t*>(Vr + 8);
                mma16(Of[j][0], Pa[0], b0, b1);
                mma16(Of[j][1], Pa[1], b0, b1);
            }
        }
        __syncthreads();
    }

    // finalize l across the 4-lane column group
    #pragma unroll
    for (int mt = 0; mt < 2; mt++)
        #pragma unroll
        for (int r = 0; r < 2; r++) {
            float s = lrow[mt][r];
            s += __shfl_xor_sync(0xffffffffu, s, 1);
            s += __shfl_xor_sync(0xffffffffu, s, 2);
            lrow[mt][r] = 1.0f / s;
        }

    __syncthreads();   // done with K/V smem; reuse as OT
    #pragma unroll
    for (int j = 0; j < 8; j++) {
        #pragma unroll
        for (int mt = 0; mt < 2; mt++) {
            int r0 = wr + mt * 16 + g;
            OT[(j * 8 + 2 * tg    ) * LDT + r0    ] = Of[j][mt][0] * lrow[mt][0];
            OT[(j * 8 + 2 * tg + 1) * LDT + r0    ] = Of[j][mt][1] * lrow[mt][0];
            OT[(j * 8 + 2 * tg    ) * LDT + r0 + 8] = Of[j][mt][2] * lrow[mt][1];
            OT[(j * 8 + 2 * tg + 1) * LDT + r0 + 8] = Of[j][mt][3] * lrow[mt][1];
        }
    }
    __syncthreads();

    // coalesced store into (B, D, N), channel = di*H + h
    #pragma unroll
    for (int cc = 0; cc < 16; cc++) {
        int di = wid * 16 + cc;
        float4 val = *reinterpret_cast<const float4*>(OT + di * LDT + lane * 4);
        *reinterpret_cast<float4*>(
            attn + ((size_t)(b * DD + di * HH + h)) * N + n0 + lane * 4) = val;
    }
}

// ---------------------------------------------------------------------------
// Shared tf32 GEMM body (tile 128x128, BK=32, double-buffered cp.async,
// 8 warps, warp tile 64x32). W pre-rounded tf32 (raw-bit A fragments).
// ---------------------------------------------------------------------------
#define LDWM 36
#define LDXM 136

struct GemmOut {
    float acc[4][4][4];
    int o0, n0, wo, wn, g, tg;
};

__device__ __forceinline__ void gemm_body(
    const float* __restrict__ W, const float* __restrict__ X0, int C0,
    const float* __restrict__ X1, int b, int IC, int N,
    int o0, int n0, float* sm, GemmOut& R)
{
    float* Ws = sm;
    float* Xs = sm + 2 * 128 * LDWM;

    const int t  = threadIdx.x;
    const int wid = t >> 5, lane = t & 31;
    R.g = lane >> 2; R.tg = lane & 3;
    R.wo = (wid & 1) * 64;
    R.wn = (wid >> 1) * 32;
    R.o0 = o0; R.n0 = n0;

    auto stage = [&](int buf, int k0) {
        uint32_t wd = smem_u32(Ws + buf * 128 * LDWM);
        uint32_t xd = smem_u32(Xs + buf * 32 * LDXM);
        #pragma unroll
        for (int i = 0; i < 4; i++) {
            int idx = t + i * 256;
            int r = idx >> 3, c = (idx & 7) * 4;
            cp16(wd + (uint32_t)(r * LDWM + c) * 4,
                 W + (size_t)(o0 + r) * IC + k0 + c);
        }
        #pragma unroll
        for (int i = 0; i < 4; i++) {
            int idx = t + i * 256;
            int r = idx >> 5, c = (idx & 31) * 4;
            int ch = k0 + r;
            const float* src = (ch < C0)
                ? (X0 + ((size_t)b * C0 + ch) * N)
                : (X1 + ((size_t)b * (IC - C0) + (ch - C0)) * N);
            cp16(xd + (uint32_t)(r * LDXM + c) * 4, src + n0 + c);
        }
        CP_COMMIT();
    };

    stage(0, 0);
    #pragma unroll
    for (int a = 0; a < 4; a++)
        #pragma unroll
        for (int c = 0; c < 4; c++)
            #pragma unroll
            for (int d = 0; d < 4; d++) R.acc[a][c][d] = 0.f;

    const int nK = IC / 32;
    for (int kt = 0; kt < nK; kt++) {
        if (kt + 1 < nK) { stage((kt + 1) & 1, (kt + 1) * 32); CP_WAIT(1); }
        else             { CP_WAIT(0); }
        __syncthreads();
        const float* Wc = Ws + (kt & 1) * 128 * LDWM;
        const float* Xc = Xs + (kt & 1) * 32 * LDXM;

        #pragma unroll
        for (int ks = 0; ks < 4; ks++) {
            uint32_t Af[4][4];
            #pragma unroll
            for (int mt = 0; mt < 4; mt++) {
                int r0 = R.wo + mt * 16 + R.g;
                Af[mt][0] = __float_as_uint(Wc[(r0    ) * LDWM + ks * 8 + R.tg]);
                Af[mt][1] = __float_as_uint(Wc[(r0 + 8) * LDWM + ks * 8 + R.tg]);
                Af[mt][2] = __float_as_uint(Wc[(r0    ) * LDWM + ks * 8 + R.tg + 4]);
                Af[mt][3] = __float_as_uint(Wc[(r0 + 8) * LDWM + ks * 8 + R.tg + 4]);
            }
            #pragma unroll
            for (int nt = 0; nt < 4; nt++) {
                uint32_t b0 = f2tf(Xc[(ks * 8 + R.tg    ) * LDXM + R.wn + nt * 8 + R.g]);
                uint32_t b1 = f2tf(Xc[(ks * 8 + R.tg + 4) * LDXM + R.wn + nt * 8 + R.g]);
                #pragma unroll
                for (int mt = 0; mt < 4; mt++)
                    mma8(R.acc[mt][nt], Af[mt], b0, b1);
            }
        }
        __syncthreads();
    }
}

// generic projection: (B,OC,N) layout
__global__ void __launch_bounds__(256)
gemm_tc(const float* __restrict__ W, const float* __restrict__ bias,
        const float* __restrict__ X0, int C0, const float* __restrict__ X1,
        float* __restrict__ out, int OC, int IC, int N)
{
    extern __shared__ float sm[];
    GemmOut R;
    gemm_body(W, X0, C0, X1, blockIdx.z, IC, N,
              blockIdx.y * 128, blockIdx.x * 128, sm, R);

    #pragma unroll
    for (int mt = 0; mt < 4; mt++) {
        int o_g  = R.o0 + R.wo + mt * 16 + R.g;
        int o_g8 = o_g + 8;
        float bg  = bias[o_g];
        float bg8 = bias[o_g8];
        #pragma unroll
        for (int nt = 0; nt < 4; nt++) {
            int n = R.n0 + R.wn + nt * 8 + 2 * R.tg;
            *reinterpret_cast<float2*>(out + ((size_t)blockIdx.z * OC + o_g ) * N + n) =
                make_float2(R.acc[mt][nt][0] + bg,  R.acc[mt][nt][1] + bg);
            *reinterpret_cast<float2*>(out + ((size_t)blockIdx.z * OC + o_g8) * N + n) =
                make_float2(R.acc[mt][nt][2] + bg8, R.acc[mt][nt][3] + bg8);
        }
    }
}

// fused Q/K/V projection: grid (N/128, D/128, 6); z = which*2 + b.
// q/k: bf16 head-permuted [b][h][n][di] (Q pre-scaled by QSCALE).
// v:   bf16 transposed    [b][h][di][m].
__global__ void __launch_bounds__(256)
gemm_qkv(const float* __restrict__ wts,
         const float* __restrict__ bq, const float* __restrict__ bk,
         const float* __restrict__ bv,
         const float* __restrict__ x, const float* __restrict__ src,
         __nv_bfloat16* __restrict__ qp, __nv_bfloat16* __restrict__ kp,
         __nv_bfloat16* __restrict__ vp, int N)
{
    extern __shared__ float sm[];
    const int z = blockIdx.z;
    const int which = z >> 1;
    const int b = z & 1;
    const float* W    = wts + which * 65536;
    const float* bias = (which == 0) ? bq : (which == 1) ? bk : bv;
    const float* X    = (which == 0) ? x : src;
    const float oscale = (which == 0) ? QSCALE : 1.0f;

    GemmOut R;
    gemm_body(W, X, DD, nullptr, b, DD, N, blockIdx.y * 128, blockIdx.x * 128, sm, R);

    #pragma unroll
    for (int mt = 0; mt < 4; mt++) {
        int o_g  = R.o0 + R.wo + mt * 16 + R.g;
        int o_g8 = o_g + 8;
        float bg  = bias[o_g];
        float bg8 = bias[o_g8];
        #pragma unroll
        for (int nt = 0; nt < 4; nt++) {
            int n = R.n0 + R.wn + nt * 8 + 2 * R.tg;
            float c0 = (R.acc[mt][nt][0] + bg)  * oscale;
            float c1 = (R.acc[mt][nt][1] + bg)  * oscale;
            float c2 = (R.acc[mt][nt][2] + bg8) * oscale;
            float c3 = (R.acc[mt][nt][3] + bg8) * oscale;
            int h0 = o_g & 3,  d0 = o_g >> 2;
            int h1 = o_g8 & 3, d1 = o_g8 >> 2;
            if (which < 2) {
                __nv_bfloat16* out = (which == 0) ? qp : kp;
                out[(((size_t)b * HH + h0) * N + n    ) * 64 + d0] = __float2bfloat16_rn(c0);
                out[(((size_t)b * HH + h0) * N + n + 1) * 64 + d0] = __float2bfloat16_rn(c1);
                out[(((size_t)b * HH + h1) * N + n    ) * 64 + d1] = __float2bfloat16_rn(c2);
                out[(((size_t)b * HH + h1) * N + n + 1) * 64 + d1] = __float2bfloat16_rn(c3);
            } else {
                // transposed: [b][h][di][m]; (n, n+1) contiguous -> packed store
                *reinterpret_cast<uint32_t*>(
                    vp + (((size_t)b * HH + h0) * 64 + d0) * N + n) = packbf(c0, c1);
                *reinterpret_cast<uint32_t*>(
                    vp + (((size_t)b * HH + h1) * 64 + d1) * N + n) = packbf(c2, c3);
            }
        }
    }
}

// ---------------------------------------------------------------------------
// InstanceNorm1d (affine=False, biased var) + ReLU, in place.
// ---------------------------------------------------------------------------
__global__ void instnorm_relu(float* __restrict__ hb, int N)
{
    int row = blockIdx.x;
    float* p = hb + (size_t)row * N;

    float s = 0.f, s2 = 0.f;
    for (int i = threadIdx.x; i < N; i += blockDim.x) {
        float v = p[i];
        s  += v;
        s2 = fmaf(v, v, s2);
    }
    #pragma unroll
    for (int off = 16; off > 0; off >>= 1) {
        s  += __shfl_xor_sync(0xffffffffu, s,  off);
        s2 += __shfl_xor_sync(0xffffffffu, s2, off);
    }
    __shared__ float sh[16];
    int wid = threadIdx.x >> 5, lid = threadIdx.x & 31;
    if (lid == 0) { sh[wid] = s; sh[wid + 8] = s2; }
    __syncthreads();
    if (threadIdx.x < 32) {
        s  = (lid < 8) ? sh[lid]     : 0.f;
        s2 = (lid < 8) ? sh[lid + 8] : 0.f;
        #pragma unroll
        for (int off = 4; off > 0; off >>= 1) {
            s  += __shfl_xor_sync(0xffffffffu, s,  off);
            s2 += __shfl_xor_sync(0xffffffffu, s2, off);
        }
        if (lid == 0) { sh[0] = s; sh[1] = s2; }
    }
    __syncthreads();
    float mean = sh[0] / (float)N;
    float var  = sh[1] / (float)N - mean * mean;
    float inv  = rsqrtf(var + 1e-5f);
    for (int i = threadIdx.x; i < N; i += blockDim.x)
        p[i] = fmaxf(0.f, (p[i] - mean) * inv);
}

// ---------------------------------------------------------------------------
extern "C" void kernel_launch(void* const* d_in, const int* in_sizes, int n_in,
                              void* d_out, int out_size)
{
    const float* x   = (const float*)d_in[0];
    const float* src = (const float*)d_in[1];
    const float* Wq  = (const float*)d_in[2];
    const float* bq  = (const float*)d_in[3];
    const float* Wk  = (const float*)d_in[4];
    const float* bk  = (const float*)d_in[5];
    const float* Wv  = (const float*)d_in[6];
    const float* bv  = (const float*)d_in[7];
    const float* Wm  = (const float*)d_in[8];
    const float* bm  = (const float*)d_in[9];
    const float* W1  = (const float*)d_in[10];
    const float* b1  = (const float*)d_in[11];
    const float* W2  = (const float*)d_in[12];
    const float* b2  = (const float*)d_in[13];

    const int B = BB, D = DD;
    const int N = in_sizes[0] / (B * D);
    const int M = in_sizes[1] / (B * D);

    __nv_bfloat16 *qp, *kp, *vp;
    float *attnp, *msgp, *hp, *wts;
    cudaGetSymbolAddress((void**)&qp,    g_q);
    cudaGetSymbolAddress((void**)&kp,    g_k);
    cudaGetSymbolAddress((void**)&vp,    g_v);
    cudaGetSymbolAddress((void**)&attnp, g_attn);
    cudaGetSymbolAddress((void**)&msgp,  g_msg);
    cudaGetSymbolAddress((void**)&hp,    g_h);
    cudaGetSymbolAddress((void**)&wts,   g_wts);

    const int gsmem = (2 * 128 * LDWM + 2 * 32 * LDXM) * (int)sizeof(float);  // 71680
    const int fsmem = 36864 + 128 * LDB * 2;                                   // 55296
    cudaFuncSetAttribute(gemm_tc,  cudaFuncAttributeMaxDynamicSharedMemorySize, gsmem);
    cudaFuncSetAttribute(gemm_qkv, cudaFuncAttributeMaxDynamicSharedMemorySize, gsmem);
    cudaFuncSetAttribute(flash_attn_bf, cudaFuncAttributeMaxDynamicSharedMemorySize, fsmem);

    // 0. round weights to tf32
    round_weights<<<(655360 + 255) / 256, 256>>>(Wq, Wk, Wv, Wm, W1, W2, wts);

    // 1. fused Q/K/V projections (bf16 outputs; Q pre-scaled; V transposed)
    gemm_qkv<<<dim3(N / 128, D / 128, 3 * B), 256, gsmem>>>(
        wts, bq, bk, bv, x, src, qp, kp, vp, N);

    // 2. fused bf16 mma attention
    flash_attn_bf<<<dim3(N / 128, HH, B), 128, fsmem>>>(qp, kp, vp, attnp, N, M);

    // 3. message projection
    gemm_tc<<<dim3(N / 128, D / 128, B), 256, gsmem>>>(
        wts + OFF_WM, bm, attnp, D, nullptr, msgp, D, D, N);

    // 4. MLP first layer on virtual concat [x; message]
    gemm_tc<<<dim3(N / 128, (2 * D) / 128, B), 256, gsmem>>>(
        wts + OFF_W1, b1, x, D, msgp, hp, 2 * D, 2 * D, N);

    // 5. InstanceNorm + ReLU
    instnorm_relu<<<B * 2 * D, 256>>>(hp, N);

    // 6. final projection -> d_out
    gemm_tc<<<dim3(N / 128, D / 128, B), 256, gsmem>>>(
        wts + OFF_W2, b2, hp, 2 * D, nullptr, (float*)d_out, D, 2 * D, N);
}